// round 1
// baseline (speedup 1.0000x reference)
#include <cuda_runtime.h>
#include <cuda_bf16.h>
#include <cstdint>

// Problem constants
#define N_TOK   16384          // B*S = 4*4096
#define D_DIM   2048
#define E_EXP   64
#define CAP     256            // N * 1.0 / E
#define KSPLIT  2

// Scratch (no allocations allowed)
__device__ float g_part[KSPLIT * E_EXP * N_TOK];   // split-K partial affinities [kz][E][N]
__device__ float g_aff[E_EXP * N_TOK];             // combined affinity [E][N]
__device__ int   g_counts[N_TOK];
__device__ float g_dummy[N_TOK * E_EXP];           // fallback if out_size is smaller than expected

// ---------------------------------------------------------------------------
// Sortable key transforms (monotone float <-> uint32)
// ---------------------------------------------------------------------------
__device__ __forceinline__ unsigned f2k(float f) {
    unsigned u = __float_as_uint(f);
    return (u >> 31) ? ~u : (u | 0x80000000u);
}
__device__ __forceinline__ float k2f(unsigned k) {
    unsigned u = (k & 0x80000000u) ? (k ^ 0x80000000u) : ~k;
    return __uint_as_float(u);
}

// ---------------------------------------------------------------------------
// Kernel 0: init outputs + counts
// ---------------------------------------------------------------------------
__global__ void init_kernel(float* __restrict__ out, int out_size, int total_main) {
    int i = blockIdx.x * blockDim.x + threadIdx.x;
    if (i < total_main) {
        if (i < out_size) out[i] = 0.0f;
    } else if (i < out_size) {
        out[i] = 256.0f;   // capacity (static int in reference)
    }
    if (i < N_TOK) g_counts[i] = 0;
}

// ---------------------------------------------------------------------------
// Kernel 1: split-K SGEMM  part[kz][e][n] = sum_{d in half kz} tokens[n][d]*w[e][d]
// BM=128 tokens x BN=64 experts per CTA, BK=16, 8x8 thread tiles, 128 threads.
// grid = (N/128, KSPLIT)
// ---------------------------------------------------------------------------
#define BM 128
#define BK 16

__global__ void __launch_bounds__(128)
gemm_kernel(const float* __restrict__ tokens, const float* __restrict__ wsel) {
    const int t  = threadIdx.x;          // 0..127
    const int n0 = blockIdx.x * BM;
    const int kz = blockIdx.y;
    const int kbeg = kz * (D_DIM / KSPLIT);
    const int kend = kbeg + (D_DIM / KSPLIT);

    __shared__ float As[BK][BM + 4];     // [k][token]
    __shared__ float Bs[BK][E_EXP + 4];  // [k][expert]

    float acc[8][8];
    #pragma unroll
    for (int j = 0; j < 8; j++)
        #pragma unroll
        for (int i = 0; i < 8; i++) acc[j][i] = 0.0f;

    const int tx = t & 15;   // token group: tokens tx*8..tx*8+7
    const int ty = t >> 4;   // expert group: experts ty*8..ty*8+7

    for (int k0 = kbeg; k0 < kend; k0 += BK) {
        // Load A tile: 128 tokens x 16 dims = 512 float4, 4 per thread
        #pragma unroll
        for (int r = 0; r < 4; r++) {
            int f   = t + r * 128;
            int row = f >> 2;            // token within tile
            int kq  = (f & 3) * 4;       // k quad
            float4 v = *(const float4*)(tokens + (size_t)(n0 + row) * D_DIM + k0 + kq);
            As[kq + 0][row] = v.x; As[kq + 1][row] = v.y;
            As[kq + 2][row] = v.z; As[kq + 3][row] = v.w;
        }
        // Load B tile: 64 experts x 16 dims = 256 float4, 2 per thread
        #pragma unroll
        for (int r = 0; r < 2; r++) {
            int f   = t + r * 128;
            int row = f >> 2;            // expert
            int kq  = (f & 3) * 4;
            float4 v = *(const float4*)(wsel + (size_t)row * D_DIM + k0 + kq);
            Bs[kq + 0][row] = v.x; Bs[kq + 1][row] = v.y;
            Bs[kq + 2][row] = v.z; Bs[kq + 3][row] = v.w;
        }
        __syncthreads();

        #pragma unroll
        for (int k = 0; k < BK; k++) {
            float a[8], b[8];
            #pragma unroll
            for (int i = 0; i < 8; i++) a[i] = As[k][tx * 8 + i];
            #pragma unroll
            for (int j = 0; j < 8; j++) b[j] = Bs[k][ty * 8 + j];
            #pragma unroll
            for (int j = 0; j < 8; j++)
                #pragma unroll
                for (int i = 0; i < 8; i++) acc[j][i] += a[i] * b[j];
        }
        __syncthreads();
    }

    float* dst = g_part + (size_t)kz * (E_EXP * N_TOK);
    #pragma unroll
    for (int j = 0; j < 8; j++) {
        int e = ty * 8 + j;
        float* rowp = dst + (size_t)e * N_TOK + n0 + tx * 8;
        float4 v0 = make_float4(acc[j][0], acc[j][1], acc[j][2], acc[j][3]);
        float4 v1 = make_float4(acc[j][4], acc[j][5], acc[j][6], acc[j][7]);
        *(float4*)(rowp + 0) = v0;
        *(float4*)(rowp + 4) = v1;
    }
}

// ---------------------------------------------------------------------------
// Kernel 2: combine split-K partials
// ---------------------------------------------------------------------------
__global__ void addk_kernel() {
    int i = blockIdx.x * blockDim.x + threadIdx.x;   // float4 index
    const int total4 = (E_EXP * N_TOK) / 4;
    if (i >= total4) return;
    float4 a = ((const float4*)g_part)[i];
    float4 b = ((const float4*)(g_part + (size_t)E_EXP * N_TOK))[i];
    a.x += b.x; a.y += b.y; a.z += b.z; a.w += b.w;
    ((float4*)g_aff)[i] = a;
}

// ---------------------------------------------------------------------------
// Kernel 3: per-expert exact top-256 via 3-pass radix histogram + softmax +
// scatter. One CTA (256 threads) per expert.
// ---------------------------------------------------------------------------
__global__ void __launch_bounds__(256)
topk_kernel(float* __restrict__ out_w, float* __restrict__ out_a) {
    const int e = blockIdx.x;
    const float* row = g_aff + (size_t)e * N_TOK;
    const int t = threadIdx.x;

    __shared__ unsigned hist[2048];
    __shared__ unsigned sred[256];
    __shared__ float    fred[256];
    __shared__ unsigned eqidx[256];
    __shared__ unsigned s_neq;
    __shared__ unsigned s_b1, s_above1, s_b2, s_above2, s_T, s_needeq;
    __shared__ unsigned s_maxkey;
    __shared__ float    s_m, s_scoreT, s_inv;

    // ---- pass 1: histogram of top 11 bits + row max ----
    for (int i = t; i < 2048; i += 256) hist[i] = 0;
    if (t == 0) s_neq = 0;
    __syncthreads();
    unsigned kmax = 0;
    for (int i = t; i < N_TOK; i += 256) {
        unsigned k = f2k(row[i]);
        atomicAdd(&hist[k >> 21], 1u);
        kmax = max(kmax, k);
    }
    sred[t] = kmax;
    __syncthreads();
    for (int s = 128; s > 0; s >>= 1) {
        if (t < s) sred[t] = max(sred[t], sred[t + s]);
        __syncthreads();
    }
    if (t == 0) {
        s_maxkey = sred[0];
        unsigned cum = 0; int b = 2047;
        for (; b >= 0; b--) { if (cum + hist[b] >= CAP) break; cum += hist[b]; }
        s_b1 = (unsigned)b; s_above1 = cum;
    }
    __syncthreads();
    const unsigned b1 = s_b1, above1 = s_above1;

    // ---- pass 2: next 11 bits within bin b1 ----
    for (int i = t; i < 2048; i += 256) hist[i] = 0;
    __syncthreads();
    for (int i = t; i < N_TOK; i += 256) {
        unsigned k = f2k(row[i]);
        if ((k >> 21) == b1) atomicAdd(&hist[(k >> 10) & 0x7FFu], 1u);
    }
    __syncthreads();
    if (t == 0) {
        unsigned need = CAP - above1;
        unsigned cum = 0; int b = 2047;
        for (; b >= 0; b--) { if (cum + hist[b] >= need) break; cum += hist[b]; }
        s_b2 = (unsigned)b; s_above2 = above1 + cum;
    }
    __syncthreads();
    const unsigned b2 = s_b2, above2 = s_above2;
    const unsigned pref = (b1 << 11) | b2;   // top 22 bits

    // ---- pass 3: low 10 bits ----
    for (int i = t; i < 1024; i += 256) hist[i] = 0;
    __syncthreads();
    for (int i = t; i < N_TOK; i += 256) {
        unsigned k = f2k(row[i]);
        if ((k >> 10) == pref) atomicAdd(&hist[k & 0x3FFu], 1u);
    }
    __syncthreads();
    if (t == 0) {
        unsigned need = CAP - above2;
        unsigned cum = 0; int b = 1023;
        for (; b >= 0; b--) { if (cum + hist[b] >= need) break; cum += hist[b]; }
        unsigned T = (pref << 10) | (unsigned)b;
        s_T = T;
        s_needeq = CAP - (above2 + cum);
    }
    __syncthreads();
    const unsigned T = s_T;
    const unsigned need_eq = s_needeq;

    // ---- collect indices with key == T (tie-break by smallest index) ----
    for (int i = t; i < N_TOK; i += 256) {
        unsigned k = f2k(row[i]);
        if (k == T) {
            unsigned p = atomicAdd(&s_neq, 1u);
            if (p < 256) eqidx[p] = (unsigned)i;
        }
    }
    __syncthreads();
    if (t == 0) {
        unsigned ne = min(s_neq, 256u);
        // place need_eq smallest indices first (stable top_k tie order)
        for (unsigned s = 0; s < need_eq && s < ne; s++) {
            unsigned mi = s;
            for (unsigned j = s + 1; j < ne; j++)
                if (eqidx[j] < eqidx[mi]) mi = j;
            unsigned tmp = eqidx[s]; eqidx[s] = eqidx[mi]; eqidx[mi] = tmp;
        }
        s_m = k2f(s_maxkey);
        s_scoreT = k2f(T);
    }
    __syncthreads();
    const float m = s_m;

    // ---- softmax denominator over selected set ----
    float part = 0.0f;
    for (int i = t; i < N_TOK; i += 256) {
        unsigned k = f2k(row[i]);
        if (k > T) part += expf(row[i] - m);
    }
    fred[t] = part;
    __syncthreads();
    for (int s = 128; s > 0; s >>= 1) {
        if (t < s) fred[t] += fred[t + s];
        __syncthreads();
    }
    if (t == 0) {
        float sum = fred[0] + (float)need_eq * expf(s_scoreT - m);
        s_inv = 1.0f / sum;
    }
    __syncthreads();
    const float inv = s_inv;

    // ---- scatter: strictly-above-threshold tokens ----
    for (int i = t; i < N_TOK; i += 256) {
        unsigned k = f2k(row[i]);
        if (k > T) {
            float p = expf(row[i] - m) * inv;
            out_w[(size_t)i * E_EXP + e] = p;
            out_a[(size_t)i * E_EXP + e] = 1.0f;
            atomicAdd(&g_counts[i], 1);
        }
    }
    // ---- scatter: equal-to-threshold tokens, lowest indices first ----
    unsigned ne = min(s_neq, 256u);
    if (t < (int)need_eq && t < (int)ne) {
        unsigned i = eqidx[t];
        float p = expf(s_scoreT - m) * inv;
        out_w[(size_t)i * E_EXP + e] = p;
        out_a[(size_t)i * E_EXP + e] = 1.0f;
        atomicAdd(&g_counts[i], 1);
    }
}

// ---------------------------------------------------------------------------
// Kernel 4: divide each token's weight row by its expert count (if >= 2)
// ---------------------------------------------------------------------------
__global__ void norm_kernel(float* __restrict__ out_w) {
    int n = blockIdx.x * blockDim.x + threadIdx.x;
    if (n >= N_TOK) return;
    int c = g_counts[n];
    if (c > 1) {
        float fc = (float)c;
        float4* p = (float4*)(out_w + (size_t)n * E_EXP);
        #pragma unroll
        for (int j = 0; j < E_EXP / 4; j++) {
            float4 v = p[j];
            v.x /= fc; v.y /= fc; v.z /= fc; v.w /= fc;
            p[j] = v;
        }
    }
}

// ---------------------------------------------------------------------------
// launch
// ---------------------------------------------------------------------------
extern "C" void kernel_launch(void* const* d_in, const int* in_sizes, int n_in,
                              void* d_out, int out_size) {
    const float* tokens = (const float*)d_in[0];   // [4,4096,2048] fp32
    const float* wsel   = (const float*)d_in[1];   // [64,2048] fp32
    float* out = (float*)d_out;

    const int total_main = 2 * N_TOK * E_EXP;      // weights + assignments

    float* out_w;
    float* out_a;
    float* dummy_ptr = nullptr;
    cudaGetSymbolAddress((void**)&dummy_ptr, g_dummy);
    if (out_size >= total_main) {
        out_w = out;
        out_a = out + (size_t)N_TOK * E_EXP;
    } else if (out_size >= N_TOK * E_EXP) {
        out_w = out;
        out_a = dummy_ptr;
    } else {
        out_w = dummy_ptr;
        out_a = dummy_ptr;
    }

    // 0) init outputs (poisoned to 0xAA by harness) + counts
    {
        int tmax = out_size > total_main ? out_size : total_main;
        int blocks = (tmax + 255) / 256;
        init_kernel<<<blocks, 256>>>(out, out_size, total_main);
    }
    // 1) split-K SGEMM
    {
        dim3 grid(N_TOK / BM, KSPLIT);
        gemm_kernel<<<grid, 128>>>(tokens, wsel);
    }
    // 2) combine partials
    {
        int total4 = (E_EXP * N_TOK) / 4;
        addk_kernel<<<(total4 + 255) / 256, 256>>>();
    }
    // 3) per-expert top-256 + softmax + scatter
    topk_kernel<<<E_EXP, 256>>>(out_w, out_a);
    // 4) normalize by per-token expert counts
    norm_kernel<<<(N_TOK + 255) / 256, 256>>>(out_w);
}

// round 2
// speedup vs baseline: 1.0646x; 1.0646x over previous
#include <cuda_runtime.h>
#include <cuda_bf16.h>
#include <cstdint>

// Problem constants
#define N_TOK   16384          // B*S = 4*4096
#define D_DIM   2048
#define E_EXP   64
#define CAP     256            // N * 1.0 / E
#define KSPLIT  2

// GEMM tiling
#define BM 128
#define BN 64
#define BK 16

// Scratch (no allocations allowed)
__device__ float g_part[KSPLIT * E_EXP * N_TOK];   // split-K partial affinities [kz][E][N]
__device__ int   g_counts[N_TOK];
__device__ float g_dummy[N_TOK * E_EXP];           // fallback if out_size is smaller than expected

// ---------------------------------------------------------------------------
// Sortable key transforms (monotone float <-> uint32)
// ---------------------------------------------------------------------------
__device__ __forceinline__ unsigned f2k(float f) {
    unsigned u = __float_as_uint(f);
    return (u >> 31) ? ~u : (u | 0x80000000u);
}
__device__ __forceinline__ float k2f(unsigned k) {
    unsigned u = (k & 0x80000000u) ? (k ^ 0x80000000u) : ~k;
    return __uint_as_float(u);
}

// ---------------------------------------------------------------------------
// Kernel 0: init outputs + counts
// ---------------------------------------------------------------------------
__global__ void init_kernel(float* __restrict__ out, int out_size, int total_main) {
    int i = blockIdx.x * blockDim.x + threadIdx.x;
    if (i < total_main) {
        if (i < out_size) out[i] = 0.0f;
    } else if (i < out_size) {
        out[i] = 256.0f;   // capacity (static python int in reference)
    }
    if (i < N_TOK) g_counts[i] = 0;
}

// ---------------------------------------------------------------------------
// Kernel 1: split-K SGEMM  part[kz][e][n] = sum_{d in half kz} tokens[n][d]*w[e][d]
// BM=128 tokens x BN=64 experts (all experts) per CTA, BK=16.
// 256 threads, 8-token x 4-expert thread tiles. grid = (N/128, KSPLIT).
// ---------------------------------------------------------------------------
__global__ void __launch_bounds__(256)
gemm_kernel(const float* __restrict__ tokens, const float* __restrict__ wsel) {
    const int t  = threadIdx.x;          // 0..255
    const int n0 = blockIdx.x * BM;
    const int kz = blockIdx.y;
    const int kbeg = kz * (D_DIM / KSPLIT);
    const int kend = kbeg + (D_DIM / KSPLIT);

    __shared__ float As[BK][BM + 4];     // [k][token]
    __shared__ float Bs[BK][BN + 4];     // [k][expert]

    float acc[4][8];                     // [expert j][token i]
    #pragma unroll
    for (int j = 0; j < 4; j++)
        #pragma unroll
        for (int i = 0; i < 8; i++) acc[j][i] = 0.0f;

    const int tx = t & 15;   // token group: tokens tx*8..tx*8+7
    const int ty = t >> 4;   // expert group: experts ty*4..ty*4+3

    for (int k0 = kbeg; k0 < kend; k0 += BK) {
        // Load A tile: 128 tokens x 16 dims = 512 float4, 2 per thread
        #pragma unroll
        for (int r = 0; r < 2; r++) {
            int f   = t + r * 256;
            int row = f >> 2;            // token within tile (0..127)
            int kq  = (f & 3) * 4;       // k quad
            float4 v = *(const float4*)(tokens + (size_t)(n0 + row) * D_DIM + k0 + kq);
            As[kq + 0][row] = v.x; As[kq + 1][row] = v.y;
            As[kq + 2][row] = v.z; As[kq + 3][row] = v.w;
        }
        // Load B tile: 64 experts x 16 dims = 256 float4, 1 per thread
        {
            int row = t >> 2;            // expert (0..63)
            int kq  = (t & 3) * 4;
            float4 v = *(const float4*)(wsel + (size_t)row * D_DIM + k0 + kq);
            Bs[kq + 0][row] = v.x; Bs[kq + 1][row] = v.y;
            Bs[kq + 2][row] = v.z; Bs[kq + 3][row] = v.w;
        }
        __syncthreads();

        #pragma unroll
        for (int k = 0; k < BK; k++) {
            float4 a0 = *(const float4*)&As[k][tx * 8];
            float4 a1 = *(const float4*)&As[k][tx * 8 + 4];
            float4 bv = *(const float4*)&Bs[k][ty * 4];
            float a[8] = {a0.x, a0.y, a0.z, a0.w, a1.x, a1.y, a1.z, a1.w};
            float b[4] = {bv.x, bv.y, bv.z, bv.w};
            #pragma unroll
            for (int j = 0; j < 4; j++)
                #pragma unroll
                for (int i = 0; i < 8; i++) acc[j][i] += a[i] * b[j];
        }
        __syncthreads();
    }

    float* dst = g_part + (size_t)kz * (E_EXP * N_TOK);
    #pragma unroll
    for (int j = 0; j < 4; j++) {
        int e = ty * 4 + j;
        float* rowp = dst + (size_t)e * N_TOK + n0 + tx * 8;
        float4 v0 = make_float4(acc[j][0], acc[j][1], acc[j][2], acc[j][3]);
        float4 v1 = make_float4(acc[j][4], acc[j][5], acc[j][6], acc[j][7]);
        *(float4*)(rowp + 0) = v0;
        *(float4*)(rowp + 4) = v1;
    }
}

// ---------------------------------------------------------------------------
// Kernel 2: per-expert exact top-256 + softmax + scatter.
// One CTA (1024 threads) per expert. Fuses the split-K combine (reads both
// partial halves, adds, caches the combined row in dynamic smem). All radix
// passes then run from smem.
// ---------------------------------------------------------------------------
__global__ void __launch_bounds__(1024)
topk_kernel(float* __restrict__ out_w, float* __restrict__ out_a) {
    extern __shared__ float scores[];          // N_TOK floats = 64 KB

    __shared__ unsigned hist[2048];
    __shared__ unsigned gsum[64];
    __shared__ unsigned wred[32];
    __shared__ float    fwred[32];
    __shared__ unsigned eqidx[256];
    __shared__ unsigned s_neq;
    __shared__ unsigned s_b1, s_ab1, s_b2, s_ab2, s_T, s_needeq, s_maxkey;
    __shared__ float    s_m, s_scoreT, s_inv;

    const int e = blockIdx.x;
    const int t = threadIdx.x;
    const float* p0 = g_part + (size_t)e * N_TOK;
    const float* p1 = g_part + (size_t)(E_EXP + e) * N_TOK;

    // ---- pass 1: load + combine + histogram (top 11 bits) + row max ----
    for (int i = t; i < 2048; i += 1024) hist[i] = 0;
    if (t == 0) s_neq = 0;
    __syncthreads();

    unsigned kmax = 0;
    for (int i = t; i < N_TOK; i += 1024) {
        float s = p0[i] + p1[i];
        scores[i] = s;
        unsigned k = f2k(s);
        kmax = max(kmax, k);
        unsigned bin = k >> 21;
        // warp-aggregated histogram update (hot Gaussian bins)
        unsigned mask = __match_any_sync(0xFFFFFFFFu, bin);
        int leader = __ffs(mask) - 1;
        if ((t & 31) == leader) atomicAdd(&hist[bin], (unsigned)__popc(mask));
    }
    #pragma unroll
    for (int o = 16; o; o >>= 1) kmax = max(kmax, __shfl_xor_sync(0xFFFFFFFFu, kmax, o));
    if ((t & 31) == 0) wred[t >> 5] = kmax;
    __syncthreads();
    if (t < 32) {
        unsigned v = wred[t];
        #pragma unroll
        for (int o = 16; o; o >>= 1) v = max(v, __shfl_xor_sync(0xFFFFFFFFu, v, o));
        if (t == 0) s_maxkey = v;
    }
    // select pass-1 bin: 2-level scan (64 groups of 32)
    if (t < 64) { unsigned s = 0; for (int j = 0; j < 32; j++) s += hist[t * 32 + j]; gsum[t] = s; }
    __syncthreads();
    if (t == 0) {
        unsigned need = CAP, cum = 0; int g = 63;
        for (; g > 0; g--) { if (cum + gsum[g] >= need) break; cum += gsum[g]; }
        int b = g * 32 + 31;
        for (; b > g * 32; b--) { if (cum + hist[b] >= need) break; cum += hist[b]; }
        s_b1 = (unsigned)b; s_ab1 = cum;
    }
    __syncthreads();
    const unsigned b1 = s_b1, ab1 = s_ab1;

    // ---- pass 2: next 11 bits within bin b1 (from smem) ----
    __syncthreads();
    for (int i = t; i < 2048; i += 1024) hist[i] = 0;
    __syncthreads();
    for (int i = t; i < N_TOK; i += 1024) {
        unsigned k = f2k(scores[i]);
        if ((k >> 21) == b1) atomicAdd(&hist[(k >> 10) & 0x7FFu], 1u);
    }
    __syncthreads();
    if (t < 64) { unsigned s = 0; for (int j = 0; j < 32; j++) s += hist[t * 32 + j]; gsum[t] = s; }
    __syncthreads();
    if (t == 0) {
        unsigned need = CAP - ab1, cum = 0; int g = 63;
        for (; g > 0; g--) { if (cum + gsum[g] >= need) break; cum += gsum[g]; }
        int b = g * 32 + 31;
        for (; b > g * 32; b--) { if (cum + hist[b] >= need) break; cum += hist[b]; }
        s_b2 = (unsigned)b; s_ab2 = ab1 + cum;
    }
    __syncthreads();
    const unsigned b2 = s_b2, ab2 = s_ab2;
    const unsigned pref = (b1 << 11) | b2;   // top 22 bits

    // ---- pass 3: low 10 bits ----
    __syncthreads();
    for (int i = t; i < 1024; i += 1024) hist[i] = 0;
    __syncthreads();
    for (int i = t; i < N_TOK; i += 1024) {
        unsigned k = f2k(scores[i]);
        if ((k >> 10) == pref) atomicAdd(&hist[k & 0x3FFu], 1u);
    }
    __syncthreads();
    if (t < 32) { unsigned s = 0; for (int j = 0; j < 32; j++) s += hist[t * 32 + j]; gsum[t] = s; }
    __syncthreads();
    if (t == 0) {
        unsigned need = CAP - ab2, cum = 0; int g = 31;
        for (; g > 0; g--) { if (cum + gsum[g] >= need) break; cum += gsum[g]; }
        int b = g * 32 + 31;
        for (; b > g * 32; b--) { if (cum + hist[b] >= need) break; cum += hist[b]; }
        unsigned T = (pref << 10) | (unsigned)b;
        s_T = T;
        s_needeq = CAP - (ab2 + cum);
    }
    __syncthreads();
    const unsigned T = s_T;
    const unsigned need_eq = s_needeq;

    // ---- collect indices with key == T (tie-break by smallest index) ----
    for (int i = t; i < N_TOK; i += 1024) {
        if (f2k(scores[i]) == T) {
            unsigned p = atomicAdd(&s_neq, 1u);
            if (p < 256) eqidx[p] = (unsigned)i;
        }
    }
    __syncthreads();
    if (t == 0) {
        unsigned ne = min(s_neq, 256u);
        for (unsigned s = 0; s < need_eq && s < ne; s++) {
            unsigned mi = s;
            for (unsigned j = s + 1; j < ne; j++)
                if (eqidx[j] < eqidx[mi]) mi = j;
            unsigned tmp = eqidx[s]; eqidx[s] = eqidx[mi]; eqidx[mi] = tmp;
        }
        s_m = k2f(s_maxkey);
        s_scoreT = k2f(T);
    }
    __syncthreads();
    const float m = s_m;

    // ---- softmax denominator over selected set ----
    float part = 0.0f;
    for (int i = t; i < N_TOK; i += 1024) {
        if (f2k(scores[i]) > T) part += expf(scores[i] - m);
    }
    #pragma unroll
    for (int o = 16; o; o >>= 1) part += __shfl_xor_sync(0xFFFFFFFFu, part, o);
    if ((t & 31) == 0) fwred[t >> 5] = part;
    __syncthreads();
    if (t < 32) {
        float v = fwred[t];
        #pragma unroll
        for (int o = 16; o; o >>= 1) v += __shfl_xor_sync(0xFFFFFFFFu, v, o);
        if (t == 0) s_inv = 1.0f / (v + (float)need_eq * expf(s_scoreT - m));
    }
    __syncthreads();
    const float inv = s_inv;

    // ---- scatter: strictly-above-threshold tokens ----
    for (int i = t; i < N_TOK; i += 1024) {
        if (f2k(scores[i]) > T) {
            float p = expf(scores[i] - m) * inv;
            out_w[(size_t)i * E_EXP + e] = p;
            out_a[(size_t)i * E_EXP + e] = 1.0f;
            atomicAdd(&g_counts[i], 1);
        }
    }
    // ---- scatter: equal-to-threshold tokens, lowest indices first ----
    unsigned ne = min(s_neq, 256u);
    if (t < (int)need_eq && t < (int)ne) {
        unsigned i = eqidx[t];
        float p = expf(s_scoreT - m) * inv;
        out_w[(size_t)i * E_EXP + e] = p;
        out_a[(size_t)i * E_EXP + e] = 1.0f;
        atomicAdd(&g_counts[i], 1);
    }
}

// ---------------------------------------------------------------------------
// Kernel 3: divide each token's weight row by its expert count (if >= 2)
// ---------------------------------------------------------------------------
__global__ void norm_kernel(float* __restrict__ out_w) {
    int n = blockIdx.x * blockDim.x + threadIdx.x;
    if (n >= N_TOK) return;
    int c = g_counts[n];
    if (c > 1) {
        float fc = (float)c;
        float4* p = (float4*)(out_w + (size_t)n * E_EXP);
        #pragma unroll
        for (int j = 0; j < E_EXP / 4; j++) {
            float4 v = p[j];
            v.x /= fc; v.y /= fc; v.z /= fc; v.w /= fc;
            p[j] = v;
        }
    }
}

// ---------------------------------------------------------------------------
// launch
// ---------------------------------------------------------------------------
extern "C" void kernel_launch(void* const* d_in, const int* in_sizes, int n_in,
                              void* d_out, int out_size) {
    const float* tokens = (const float*)d_in[0];   // [4,4096,2048] fp32
    const float* wsel   = (const float*)d_in[1];   // [64,2048] fp32
    float* out = (float*)d_out;

    const int total_main = 2 * N_TOK * E_EXP;      // weights + assignments

    float* out_w;
    float* out_a;
    float* dummy_ptr = nullptr;
    cudaGetSymbolAddress((void**)&dummy_ptr, g_dummy);
    if (out_size >= total_main) {
        out_w = out;
        out_a = out + (size_t)N_TOK * E_EXP;
    } else if (out_size >= N_TOK * E_EXP) {
        out_w = out;
        out_a = dummy_ptr;
    } else {
        out_w = dummy_ptr;
        out_a = dummy_ptr;
    }

    // allow 64KB dynamic smem for the score cache (idempotent, capture-safe)
    cudaFuncSetAttribute(topk_kernel, cudaFuncAttributeMaxDynamicSharedMemorySize,
                         N_TOK * sizeof(float));

    // 0) init outputs (poisoned to 0xAA by harness) + counts
    {
        int tmax = out_size > total_main ? out_size : total_main;
        int blocks = (tmax + 255) / 256;
        init_kernel<<<blocks, 256>>>(out, out_size, total_main);
    }
    // 1) split-K SGEMM
    {
        dim3 grid(N_TOK / BM, KSPLIT);
        gemm_kernel<<<grid, 256>>>(tokens, wsel);
    }
    // 2) per-expert top-256 + softmax + scatter (fuses split-K combine)
    topk_kernel<<<E_EXP, 1024, N_TOK * sizeof(float)>>>(out_w, out_a);
    // 3) normalize by per-token expert counts
    norm_kernel<<<(N_TOK + 255) / 256, 256>>>(out_w);
}

// round 3
// speedup vs baseline: 1.3575x; 1.2752x over previous
#include <cuda_runtime.h>
#include <cuda_bf16.h>
#include <cstdint>

// Problem constants
#define N_TOK   16384          // B*S = 4*4096
#define D_DIM   2048
#define E_EXP   64
#define CAP     256            // N * 1.0 / E
#define KSPLIT  4

// GEMM tiling
#define BM 64
#define BN 64
#define BK 16

// Scratch (no allocations allowed)
__device__ float    g_part[KSPLIT * E_EXP * N_TOK];  // split-K partials [kz][E][N]
__device__ int      g_counts[N_TOK];
__device__ unsigned g_sel_idx[E_EXP * CAP];          // compact selected token idx
__device__ float    g_sel_prob[E_EXP * CAP];         // compact softmax prob
__device__ float    g_dummy[N_TOK * E_EXP];

// ---------------------------------------------------------------------------
// Sortable key transforms (monotone float <-> uint32)
// ---------------------------------------------------------------------------
__device__ __forceinline__ unsigned f2k(float f) {
    unsigned u = __float_as_uint(f);
    return (u >> 31) ? ~u : (u | 0x80000000u);
}
__device__ __forceinline__ float k2f(unsigned k) {
    unsigned u = (k & 0x80000000u) ? (k ^ 0x80000000u) : ~k;
    return __uint_as_float(u);
}

// ---------------------------------------------------------------------------
// Kernel 0: init outputs + counts (out poisoned to 0xAA by harness)
// ---------------------------------------------------------------------------
__global__ void init_kernel(float* __restrict__ out, int out_size, int total_main) {
    int base = (blockIdx.x * blockDim.x + threadIdx.x) * 4;
    #pragma unroll
    for (int j = 0; j < 4; j++) {
        int i = base + j;
        if (i < out_size) out[i] = (i < total_main) ? 0.0f : 256.0f;
    }
    int n = blockIdx.x * blockDim.x + threadIdx.x;
    if (n < N_TOK) g_counts[n] = 0;
}

// ---------------------------------------------------------------------------
// Kernel 1: split-K SGEMM  part[kz][e][n] = sum_{d in slice kz} tok[n][d]*w[e][d]
// BM=64 tokens x BN=64 experts, BK=16, 128 threads, 8x4 thread tiles.
// Register-prefetch double buffering. grid = (N/64, KSPLIT) = (256,4).
// ---------------------------------------------------------------------------
__global__ void __launch_bounds__(128)
gemm_kernel(const float* __restrict__ tokens, const float* __restrict__ wsel) {
    const int t  = threadIdx.x;              // 0..127
    const int n0 = blockIdx.x * BM;
    int k0 = blockIdx.y * (D_DIM / KSPLIT);
    const int kend = k0 + (D_DIM / KSPLIT);

    __shared__ float As[BK][BM + 4];         // [k][token]
    __shared__ float Bs[BK][BN + 4];         // [k][expert]

    // load addressing: A tile 64x16 = 256 float4, 2/thread; B same
    const int rA0 = t >> 2,          kqA0 = (t & 3) * 4;
    const int rA1 = (t + 128) >> 2,  kqA1 = ((t + 128) & 3) * 4;

    const float* aP0 = tokens + (size_t)(n0 + rA0) * D_DIM + kqA0;
    const float* aP1 = tokens + (size_t)(n0 + rA1) * D_DIM + kqA1;
    const float* bP0 = wsel   + (size_t)rA0 * D_DIM + kqA0;
    const float* bP1 = wsel   + (size_t)rA1 * D_DIM + kqA1;

    float acc[4][8];
    #pragma unroll
    for (int j = 0; j < 4; j++)
        #pragma unroll
        for (int i = 0; i < 8; i++) acc[j][i] = 0.0f;

    const int tx = t & 7;    // token group: tokens tx*8..tx*8+7
    const int ty = t >> 3;   // expert group: experts ty*4..ty*4+3

    // prefetch first tile
    float4 pa0 = *(const float4*)(aP0 + k0);
    float4 pa1 = *(const float4*)(aP1 + k0);
    float4 pb0 = *(const float4*)(bP0 + k0);
    float4 pb1 = *(const float4*)(bP1 + k0);

    for (; k0 < kend; k0 += BK) {
        As[kqA0 + 0][rA0] = pa0.x; As[kqA0 + 1][rA0] = pa0.y;
        As[kqA0 + 2][rA0] = pa0.z; As[kqA0 + 3][rA0] = pa0.w;
        As[kqA1 + 0][rA1] = pa1.x; As[kqA1 + 1][rA1] = pa1.y;
        As[kqA1 + 2][rA1] = pa1.z; As[kqA1 + 3][rA1] = pa1.w;
        Bs[kqA0 + 0][rA0] = pb0.x; Bs[kqA0 + 1][rA0] = pb0.y;
        Bs[kqA0 + 2][rA0] = pb0.z; Bs[kqA0 + 3][rA0] = pb0.w;
        Bs[kqA1 + 0][rA1] = pb1.x; Bs[kqA1 + 1][rA1] = pb1.y;
        Bs[kqA1 + 2][rA1] = pb1.z; Bs[kqA1 + 3][rA1] = pb1.w;
        __syncthreads();

        int kn = k0 + BK;
        if (kn < kend) {   // prefetch next tile while computing this one
            pa0 = *(const float4*)(aP0 + kn);
            pa1 = *(const float4*)(aP1 + kn);
            pb0 = *(const float4*)(bP0 + kn);
            pb1 = *(const float4*)(bP1 + kn);
        }

        #pragma unroll
        for (int k = 0; k < BK; k++) {
            float4 a0 = *(const float4*)&As[k][tx * 8];
            float4 a1 = *(const float4*)&As[k][tx * 8 + 4];
            float4 bv = *(const float4*)&Bs[k][ty * 4];
            float a[8] = {a0.x, a0.y, a0.z, a0.w, a1.x, a1.y, a1.z, a1.w};
            float b[4] = {bv.x, bv.y, bv.z, bv.w};
            #pragma unroll
            for (int j = 0; j < 4; j++)
                #pragma unroll
                for (int i = 0; i < 8; i++) acc[j][i] += a[i] * b[j];
        }
        __syncthreads();
    }

    float* dst = g_part + (size_t)blockIdx.y * (E_EXP * N_TOK);
    #pragma unroll
    for (int j = 0; j < 4; j++) {
        int e = ty * 4 + j;
        float* rowp = dst + (size_t)e * N_TOK + n0 + tx * 8;
        *(float4*)(rowp + 0) = make_float4(acc[j][0], acc[j][1], acc[j][2], acc[j][3]);
        *(float4*)(rowp + 4) = make_float4(acc[j][4], acc[j][5], acc[j][6], acc[j][7]);
    }
}

// ---------------------------------------------------------------------------
// Kernel 2: per-expert exact top-256 + softmax -> compact lists + counts.
// One CTA (1024 threads) per expert; fuses split-K combine; smem score cache.
// ---------------------------------------------------------------------------
__global__ void __launch_bounds__(1024)
topk_kernel() {
    extern __shared__ float scores[];          // N_TOK floats = 64 KB

    __shared__ unsigned hist[2048];
    __shared__ unsigned gsum[64];
    __shared__ unsigned wred[32];
    __shared__ float    fwred[32];
    __shared__ unsigned eqidx[256];
    __shared__ unsigned s_neq, s_na;
    __shared__ unsigned s_b1, s_ab1, s_b2, s_ab2, s_T, s_needeq, s_maxkey;
    __shared__ float    s_m, s_scoreT, s_inv;

    const int e = blockIdx.x;
    const int t = threadIdx.x;
    const float* p0 = g_part + (size_t)(0 * E_EXP + e) * N_TOK;
    const float* p1 = g_part + (size_t)(1 * E_EXP + e) * N_TOK;
    const float* p2 = g_part + (size_t)(2 * E_EXP + e) * N_TOK;
    const float* p3 = g_part + (size_t)(3 * E_EXP + e) * N_TOK;

    // ---- pass 1: load + combine + histogram (top 11 bits) + row max ----
    for (int i = t; i < 2048; i += 1024) hist[i] = 0;
    if (t == 0) { s_neq = 0; s_na = 0; }
    __syncthreads();

    unsigned kmax = 0;
    for (int i = t; i < N_TOK; i += 1024) {
        float s = (p0[i] + p1[i]) + (p2[i] + p3[i]);
        scores[i] = s;
        unsigned k = f2k(s);
        kmax = max(kmax, k);
        unsigned bin = k >> 21;
        unsigned mask = __match_any_sync(0xFFFFFFFFu, bin);
        int leader = __ffs(mask) - 1;
        if ((t & 31) == leader) atomicAdd(&hist[bin], (unsigned)__popc(mask));
    }
    #pragma unroll
    for (int o = 16; o; o >>= 1) kmax = max(kmax, __shfl_xor_sync(0xFFFFFFFFu, kmax, o));
    if ((t & 31) == 0) wred[t >> 5] = kmax;
    __syncthreads();
    if (t < 32) {
        unsigned v = wred[t];
        #pragma unroll
        for (int o = 16; o; o >>= 1) v = max(v, __shfl_xor_sync(0xFFFFFFFFu, v, o));
        if (t == 0) s_maxkey = v;
    }
    if (t < 64) { unsigned s = 0; for (int j = 0; j < 32; j++) s += hist[t * 32 + j]; gsum[t] = s; }
    __syncthreads();
    if (t == 0) {
        unsigned need = CAP, cum = 0; int g = 63;
        for (; g > 0; g--) { if (cum + gsum[g] >= need) break; cum += gsum[g]; }
        int b = g * 32 + 31;
        for (; b > g * 32; b--) { if (cum + hist[b] >= need) break; cum += hist[b]; }
        s_b1 = (unsigned)b; s_ab1 = cum;
    }
    __syncthreads();
    const unsigned b1 = s_b1, ab1 = s_ab1;

    // ---- pass 2: next 11 bits within bin b1 ----
    __syncthreads();
    for (int i = t; i < 2048; i += 1024) hist[i] = 0;
    __syncthreads();
    for (int i = t; i < N_TOK; i += 1024) {
        unsigned k = f2k(scores[i]);
        if ((k >> 21) == b1) atomicAdd(&hist[(k >> 10) & 0x7FFu], 1u);
    }
    __syncthreads();
    if (t < 64) { unsigned s = 0; for (int j = 0; j < 32; j++) s += hist[t * 32 + j]; gsum[t] = s; }
    __syncthreads();
    if (t == 0) {
        unsigned need = CAP - ab1, cum = 0; int g = 63;
        for (; g > 0; g--) { if (cum + gsum[g] >= need) break; cum += gsum[g]; }
        int b = g * 32 + 31;
        for (; b > g * 32; b--) { if (cum + hist[b] >= need) break; cum += hist[b]; }
        s_b2 = (unsigned)b; s_ab2 = ab1 + cum;
    }
    __syncthreads();
    const unsigned b2 = s_b2, ab2 = s_ab2;
    const unsigned pref = (b1 << 11) | b2;

    // ---- pass 3: low 10 bits ----
    __syncthreads();
    if (t < 1024) hist[t] = 0;
    __syncthreads();
    for (int i = t; i < N_TOK; i += 1024) {
        unsigned k = f2k(scores[i]);
        if ((k >> 10) == pref) atomicAdd(&hist[k & 0x3FFu], 1u);
    }
    __syncthreads();
    if (t < 32) { unsigned s = 0; for (int j = 0; j < 32; j++) s += hist[t * 32 + j]; gsum[t] = s; }
    __syncthreads();
    if (t == 0) {
        unsigned need = CAP - ab2, cum = 0; int g = 31;
        for (; g > 0; g--) { if (cum + gsum[g] >= need) break; cum += gsum[g]; }
        int b = g * 32 + 31;
        for (; b > g * 32; b--) { if (cum + hist[b] >= need) break; cum += hist[b]; }
        unsigned T = (pref << 10) | (unsigned)b;
        s_T = T;
        s_needeq = CAP - (ab2 + cum);
    }
    __syncthreads();
    const unsigned T = s_T;
    const unsigned need_eq = s_needeq;

    // ---- collect indices with key == T ----
    for (int i = t; i < N_TOK; i += 1024) {
        if (f2k(scores[i]) == T) {
            unsigned p = atomicAdd(&s_neq, 1u);
            if (p < 256) eqidx[p] = (unsigned)i;
        }
    }
    __syncthreads();
    if (t == 0) {
        unsigned ne = min(s_neq, 256u);
        for (unsigned s = 0; s < need_eq && s < ne; s++) {  // smallest indices first
            unsigned mi = s;
            for (unsigned j = s + 1; j < ne; j++)
                if (eqidx[j] < eqidx[mi]) mi = j;
            unsigned tmp = eqidx[s]; eqidx[s] = eqidx[mi]; eqidx[mi] = tmp;
        }
        s_m = k2f(s_maxkey);
        s_scoreT = k2f(T);
    }
    __syncthreads();
    const float m = s_m;

    // ---- softmax denominator over selected set ----
    float part = 0.0f;
    for (int i = t; i < N_TOK; i += 1024) {
        if (f2k(scores[i]) > T) part += expf(scores[i] - m);
    }
    #pragma unroll
    for (int o = 16; o; o >>= 1) part += __shfl_xor_sync(0xFFFFFFFFu, part, o);
    if ((t & 31) == 0) fwred[t >> 5] = part;
    __syncthreads();
    if (t < 32) {
        float v = fwred[t];
        #pragma unroll
        for (int o = 16; o; o >>= 1) v += __shfl_xor_sync(0xFFFFFFFFu, v, o);
        if (t == 0) s_inv = 1.0f / (v + (float)need_eq * expf(s_scoreT - m));
    }
    __syncthreads();
    const float inv = s_inv;

    // ---- compact output: strictly-above-threshold tokens ----
    unsigned* sel_i = g_sel_idx  + (size_t)e * CAP;
    float*    sel_p = g_sel_prob + (size_t)e * CAP;
    for (int i = t; i < N_TOK; i += 1024) {
        if (f2k(scores[i]) > T) {
            unsigned pos = atomicAdd(&s_na, 1u);
            sel_i[pos] = (unsigned)i;
            sel_p[pos] = expf(scores[i] - m) * inv;
            atomicAdd(&g_counts[i], 1);
        }
    }
    __syncthreads();
    // ---- equal-to-threshold tokens fill the remaining slots ----
    unsigned ne = min(s_neq, 256u);
    if (t < (int)need_eq && t < (int)ne) {
        unsigned i = eqidx[t];
        unsigned pos = (CAP - need_eq) + t;
        sel_i[pos] = i;
        sel_p[pos] = expf(s_scoreT - m) * inv;
        atomicAdd(&g_counts[i], 1);
    }
}

// ---------------------------------------------------------------------------
// Kernel 3: emit — scatter compact lists into [N,E] outputs with count divide
// ---------------------------------------------------------------------------
__global__ void emit_kernel(float* __restrict__ out_w, float* __restrict__ out_a) {
    int idx = blockIdx.x * blockDim.x + threadIdx.x;   // 0..E*CAP-1
    if (idx >= E_EXP * CAP) return;
    int e = idx >> 8;                                  // CAP == 256
    unsigned i = g_sel_idx[idx];
    float p = g_sel_prob[idx];
    int c = g_counts[i];
    out_w[(size_t)i * E_EXP + e] = p / (float)c;
    out_a[(size_t)i * E_EXP + e] = 1.0f;
}

// ---------------------------------------------------------------------------
// launch
// ---------------------------------------------------------------------------
extern "C" void kernel_launch(void* const* d_in, const int* in_sizes, int n_in,
                              void* d_out, int out_size) {
    const float* tokens = (const float*)d_in[0];   // [4,4096,2048] fp32
    const float* wsel   = (const float*)d_in[1];   // [64,2048] fp32
    float* out = (float*)d_out;

    const int total_main = 2 * N_TOK * E_EXP;      // weights + assignments

    float* out_w;
    float* out_a;
    float* dummy_ptr = nullptr;
    cudaGetSymbolAddress((void**)&dummy_ptr, g_dummy);
    if (out_size >= total_main) {
        out_w = out;
        out_a = out + (size_t)N_TOK * E_EXP;
    } else if (out_size >= N_TOK * E_EXP) {
        out_w = out;
        out_a = dummy_ptr;
    } else {
        out_w = dummy_ptr;
        out_a = dummy_ptr;
    }

    cudaFuncSetAttribute(topk_kernel, cudaFuncAttributeMaxDynamicSharedMemorySize,
                         N_TOK * sizeof(float));

    // 0) init outputs + counts
    {
        int quads = (out_size + 3) / 4;
        int blocks = (quads + 255) / 256;
        init_kernel<<<blocks, 256>>>(out, out_size, total_main);
    }
    // 1) split-K SGEMM
    {
        dim3 grid(N_TOK / BM, KSPLIT);
        gemm_kernel<<<grid, 128>>>(tokens, wsel);
    }
    // 2) per-expert top-256 + softmax -> compact lists + counts
    topk_kernel<<<E_EXP, 1024, N_TOK * sizeof(float)>>>();
    // 3) emit outputs
    emit_kernel<<<(E_EXP * CAP + 255) / 256, 256>>>(out_w, out_a);
}

// round 8
// speedup vs baseline: 2.1981x; 1.6193x over previous
#include <cuda_runtime.h>
#include <cuda_bf16.h>
#include <cstdint>

// Problem constants
#define N_TOK   16384          // B*S = 4*4096
#define D_DIM   2048
#define E_EXP   64
#define CAP     256            // N * 1.0 / E

// GEMM tiling (mma.sync m16n8k8 tf32)
#define BMt     128            // tokens per CTA
#define BNt     64             // experts per CTA (all)
#define BKt     32             // fp32 K per chunk
#define NCHUNK  (D_DIM / BKt)  // 64
#define ASTR    36             // smem row stride (floats): 36 mod 32 = 4 -> conflict-free frags

// Scratch (no allocations allowed)
__device__ float    g_aff[E_EXP * N_TOK];            // affinity [E][N]
__device__ int      g_counts[N_TOK];
__device__ unsigned g_sel_idx[E_EXP * CAP];
__device__ float    g_sel_prob[E_EXP * CAP];
__device__ float    g_dummy[N_TOK * E_EXP];

// ---------------------------------------------------------------------------
// helpers
// ---------------------------------------------------------------------------
// cvt.rna.tf32.f32 requires a .b32 destination (fp32 bit pattern, low 13
// mantissa bits cleared).
__device__ __forceinline__ uint32_t tf32_bits(float x) {
    uint32_t r;
    asm("cvt.rna.tf32.f32 %0, %1;" : "=r"(r) : "f"(x));
    return r;
}
__device__ __forceinline__ void split(float x, uint32_t& hi, uint32_t& lo) {
    hi = tf32_bits(x);
    lo = tf32_bits(x - __uint_as_float(hi));
}
__device__ __forceinline__ void mma_tf32(float* c, const uint32_t* a, const uint32_t* b) {
    asm volatile(
        "mma.sync.aligned.m16n8k8.row.col.f32.tf32.tf32.f32 "
        "{%0,%1,%2,%3}, {%4,%5,%6,%7}, {%8,%9}, {%0,%1,%2,%3};"
        : "+f"(c[0]), "+f"(c[1]), "+f"(c[2]), "+f"(c[3])
        : "r"(a[0]), "r"(a[1]), "r"(a[2]), "r"(a[3]), "r"(b[0]), "r"(b[1]));
}

// Sortable key transforms (monotone float <-> uint32)
__device__ __forceinline__ unsigned f2k(float f) {
    unsigned u = __float_as_uint(f);
    return (u >> 31) ? ~u : (u | 0x80000000u);
}
__device__ __forceinline__ float k2f(unsigned k) {
    unsigned u = (k & 0x80000000u) ? (k ^ 0x80000000u) : ~k;
    return __uint_as_float(u);
}

// ---------------------------------------------------------------------------
// Kernel 0: init outputs + counts (out poisoned to 0xAA by harness)
// ---------------------------------------------------------------------------
__global__ void init_kernel(float* __restrict__ out, int out_size, int total_main) {
    int base = (blockIdx.x * blockDim.x + threadIdx.x) * 4;
    #pragma unroll
    for (int j = 0; j < 4; j++) {
        int i = base + j;
        if (i < out_size) out[i] = (i < total_main) ? 0.0f : 256.0f;
    }
    int n = blockIdx.x * blockDim.x + threadIdx.x;
    if (n < N_TOK) g_counts[n] = 0;
}

// ---------------------------------------------------------------------------
// Kernel 1: TF32x3 mma.sync GEMM.  g_aff[e][n] = sum_d tok[n][d]*w[e][d]
// 128 CTAs x 256 threads (8 warps, 4x2 grid, 32x32 warp tiles).
// Double-buffered smem K-chunks of 32 fp32; hi/lo tf32 split in registers.
// ---------------------------------------------------------------------------
#define GEMM_SMEM ((2 * BMt * ASTR + 2 * BNt * ASTR) * 4)   // 55296 B

__global__ void __launch_bounds__(256)
gemm_mma(const float* __restrict__ tokens, const float* __restrict__ wsel) {
    extern __shared__ float sm[];
    float* As = sm;                       // [2][BMt*ASTR]
    float* Bs = sm + 2 * BMt * ASTR;      // [2][BNt*ASTR]

    const int t    = threadIdx.x;
    const int lane = t & 31;
    const int wid  = t >> 5;
    const int warp_m = wid & 3;           // 0..3 -> token offset *32
    const int warp_n = wid >> 2;          // 0..1 -> expert offset *32
    const int g  = lane >> 2;             // 0..7
    const int tg = lane & 3;              // 0..3
    const int n0 = blockIdx.x * BMt;

    // gmem load coords: A 4 float4/thread, B 2 float4/thread
    int arow[4], akq[4];
    #pragma unroll
    for (int r = 0; r < 4; r++) { int i = t + r * 256; arow[r] = i >> 3; akq[r] = i & 7; }
    int brow[2], bkq[2];
    #pragma unroll
    for (int r = 0; r < 2; r++) { int i = t + r * 256; brow[r] = i >> 3; bkq[r] = i & 7; }

    float4 pa[4], pb[2];

    float c[2][4][4];
    #pragma unroll
    for (int mi = 0; mi < 2; mi++)
        #pragma unroll
        for (int ni = 0; ni < 4; ni++)
            #pragma unroll
            for (int q = 0; q < 4; q++) c[mi][ni][q] = 0.0f;

    // ---- prefetch chunk 0 + store to buf 0 ----
    #pragma unroll
    for (int r = 0; r < 4; r++)
        pa[r] = *(const float4*)(tokens + (size_t)(n0 + arow[r]) * D_DIM + akq[r] * 4);
    #pragma unroll
    for (int r = 0; r < 2; r++)
        pb[r] = *(const float4*)(wsel + (size_t)brow[r] * D_DIM + bkq[r] * 4);
    #pragma unroll
    for (int r = 0; r < 4; r++)
        *(float4*)(As + arow[r] * ASTR + akq[r] * 4) = pa[r];
    #pragma unroll
    for (int r = 0; r < 2; r++)
        *(float4*)(Bs + brow[r] * ASTR + bkq[r] * 4) = pb[r];
    __syncthreads();

    for (int ch = 0; ch < NCHUNK; ch++) {
        const int b = ch & 1;
        // prefetch next chunk (overlaps with compute below)
        if (ch < NCHUNK - 1) {
            const int c0 = (ch + 1) * BKt;
            #pragma unroll
            for (int r = 0; r < 4; r++)
                pa[r] = *(const float4*)(tokens + (size_t)(n0 + arow[r]) * D_DIM + c0 + akq[r] * 4);
            #pragma unroll
            for (int r = 0; r < 2; r++)
                pb[r] = *(const float4*)(wsel + (size_t)brow[r] * D_DIM + c0 + bkq[r] * 4);
        }

        const float* Ab = As + b * (BMt * ASTR);
        const float* Bb = Bs + b * (BNt * ASTR);
        #pragma unroll
        for (int ks = 0; ks < 4; ks++) {
            const int kc = ks * 8;
            uint32_t ahi[2][4], alo[2][4], bhi[4][2], blo[4][2];
            #pragma unroll
            for (int mi = 0; mi < 2; mi++) {
                int r0 = warp_m * 32 + mi * 16 + g;
                split(Ab[r0 * ASTR + kc + tg],           ahi[mi][0], alo[mi][0]);
                split(Ab[(r0 + 8) * ASTR + kc + tg],     ahi[mi][1], alo[mi][1]);
                split(Ab[r0 * ASTR + kc + tg + 4],       ahi[mi][2], alo[mi][2]);
                split(Ab[(r0 + 8) * ASTR + kc + tg + 4], ahi[mi][3], alo[mi][3]);
            }
            #pragma unroll
            for (int ni = 0; ni < 4; ni++) {
                int cb = warp_n * 32 + ni * 8 + g;
                split(Bb[cb * ASTR + kc + tg],     bhi[ni][0], blo[ni][0]);
                split(Bb[cb * ASTR + kc + tg + 4], bhi[ni][1], blo[ni][1]);
            }
            #pragma unroll
            for (int mi = 0; mi < 2; mi++)
                #pragma unroll
                for (int ni = 0; ni < 4; ni++) {
                    mma_tf32(c[mi][ni], ahi[mi], bhi[ni]);
                    mma_tf32(c[mi][ni], ahi[mi], blo[ni]);
                    mma_tf32(c[mi][ni], alo[mi], bhi[ni]);
                }
        }
        __syncthreads();
        if (ch < NCHUNK - 1) {
            float* Aw = As + (b ^ 1) * (BMt * ASTR);
            float* Bw = Bs + (b ^ 1) * (BNt * ASTR);
            #pragma unroll
            for (int r = 0; r < 4; r++)
                *(float4*)(Aw + arow[r] * ASTR + akq[r] * 4) = pa[r];
            #pragma unroll
            for (int r = 0; r < 2; r++)
                *(float4*)(Bw + brow[r] * ASTR + bkq[r] * 4) = pb[r];
            __syncthreads();
        }
    }

    // ---- epilogue: c[mi][ni] -> g_aff[e][token] ----
    #pragma unroll
    for (int mi = 0; mi < 2; mi++) {
        int tm = n0 + warp_m * 32 + mi * 16;
        #pragma unroll
        for (int ni = 0; ni < 4; ni++) {
            int en = warp_n * 32 + ni * 8 + 2 * tg;
            g_aff[(size_t)en       * N_TOK + tm + g    ] = c[mi][ni][0];
            g_aff[(size_t)(en + 1) * N_TOK + tm + g    ] = c[mi][ni][1];
            g_aff[(size_t)en       * N_TOK + tm + g + 8] = c[mi][ni][2];
            g_aff[(size_t)(en + 1) * N_TOK + tm + g + 8] = c[mi][ni][3];
        }
    }
}

// ---------------------------------------------------------------------------
// Kernel 2: per-expert exact top-256 + softmax -> compact lists + counts.
// One CTA (1024 threads) per expert; smem score cache.
// ---------------------------------------------------------------------------
__global__ void __launch_bounds__(1024)
topk_kernel() {
    extern __shared__ float scores[];          // N_TOK floats = 64 KB

    __shared__ unsigned hist[2048];
    __shared__ unsigned gsum[64];
    __shared__ unsigned wred[32];
    __shared__ float    fwred[32];
    __shared__ unsigned eqidx[256];
    __shared__ unsigned s_neq, s_na;
    __shared__ unsigned s_b1, s_ab1, s_b2, s_ab2, s_T, s_needeq, s_maxkey;
    __shared__ float    s_m, s_scoreT, s_inv;

    const int e = blockIdx.x;
    const int t = threadIdx.x;
    const float* row = g_aff + (size_t)e * N_TOK;

    // ---- pass 1: load + histogram (top 11 bits) + row max ----
    for (int i = t; i < 2048; i += 1024) hist[i] = 0;
    if (t == 0) { s_neq = 0; s_na = 0; }
    __syncthreads();

    unsigned kmax = 0;
    for (int i = t; i < N_TOK; i += 1024) {
        float s = row[i];
        scores[i] = s;
        unsigned k = f2k(s);
        kmax = max(kmax, k);
        unsigned bin = k >> 21;
        unsigned mask = __match_any_sync(0xFFFFFFFFu, bin);
        int leader = __ffs(mask) - 1;
        if ((t & 31) == leader) atomicAdd(&hist[bin], (unsigned)__popc(mask));
    }
    #pragma unroll
    for (int o = 16; o; o >>= 1) kmax = max(kmax, __shfl_xor_sync(0xFFFFFFFFu, kmax, o));
    if ((t & 31) == 0) wred[t >> 5] = kmax;
    __syncthreads();
    if (t < 32) {
        unsigned v = wred[t];
        #pragma unroll
        for (int o = 16; o; o >>= 1) v = max(v, __shfl_xor_sync(0xFFFFFFFFu, v, o));
        if (t == 0) s_maxkey = v;
    }
    if (t < 64) { unsigned s = 0; for (int j = 0; j < 32; j++) s += hist[t * 32 + j]; gsum[t] = s; }
    __syncthreads();
    if (t == 0) {
        unsigned need = CAP, cum = 0; int g = 63;
        for (; g > 0; g--) { if (cum + gsum[g] >= need) break; cum += gsum[g]; }
        int b = g * 32 + 31;
        for (; b > g * 32; b--) { if (cum + hist[b] >= need) break; cum += hist[b]; }
        s_b1 = (unsigned)b; s_ab1 = cum;
    }
    __syncthreads();
    const unsigned b1 = s_b1, ab1 = s_ab1;

    // ---- pass 2: next 11 bits within bin b1 ----
    __syncthreads();
    for (int i = t; i < 2048; i += 1024) hist[i] = 0;
    __syncthreads();
    for (int i = t; i < N_TOK; i += 1024) {
        unsigned k = f2k(scores[i]);
        if ((k >> 21) == b1) atomicAdd(&hist[(k >> 10) & 0x7FFu], 1u);
    }
    __syncthreads();
    if (t < 64) { unsigned s = 0; for (int j = 0; j < 32; j++) s += hist[t * 32 + j]; gsum[t] = s; }
    __syncthreads();
    if (t == 0) {
        unsigned need = CAP - ab1, cum = 0; int g = 63;
        for (; g > 0; g--) { if (cum + gsum[g] >= need) break; cum += gsum[g]; }
        int b = g * 32 + 31;
        for (; b > g * 32; b--) { if (cum + hist[b] >= need) break; cum += hist[b]; }
        s_b2 = (unsigned)b; s_ab2 = ab1 + cum;
    }
    __syncthreads();
    const unsigned b2 = s_b2, ab2 = s_ab2;
    const unsigned pref = (b1 << 11) | b2;

    // ---- pass 3: low 10 bits ----
    __syncthreads();
    if (t < 1024) hist[t] = 0;
    __syncthreads();
    for (int i = t; i < N_TOK; i += 1024) {
        unsigned k = f2k(scores[i]);
        if ((k >> 10) == pref) atomicAdd(&hist[k & 0x3FFu], 1u);
    }
    __syncthreads();
    if (t < 32) { unsigned s = 0; for (int j = 0; j < 32; j++) s += hist[t * 32 + j]; gsum[t] = s; }
    __syncthreads();
    if (t == 0) {
        unsigned need = CAP - ab2, cum = 0; int g = 31;
        for (; g > 0; g--) { if (cum + gsum[g] >= need) break; cum += gsum[g]; }
        int b = g * 32 + 31;
        for (; b > g * 32; b--) { if (cum + hist[b] >= need) break; cum += hist[b]; }
        unsigned T = (pref << 10) | (unsigned)b;
        s_T = T;
        s_needeq = CAP - (ab2 + cum);
    }
    __syncthreads();
    const unsigned T = s_T;
    const unsigned need_eq = s_needeq;

    // ---- collect indices with key == T ----
    for (int i = t; i < N_TOK; i += 1024) {
        if (f2k(scores[i]) == T) {
            unsigned p = atomicAdd(&s_neq, 1u);
            if (p < 256) eqidx[p] = (unsigned)i;
        }
    }
    __syncthreads();
    if (t == 0) {
        unsigned ne = min(s_neq, 256u);
        for (unsigned s = 0; s < need_eq && s < ne; s++) {  // smallest indices first
            unsigned mi = s;
            for (unsigned j = s + 1; j < ne; j++)
                if (eqidx[j] < eqidx[mi]) mi = j;
            unsigned tmp = eqidx[s]; eqidx[s] = eqidx[mi]; eqidx[mi] = tmp;
        }
        s_m = k2f(s_maxkey);
        s_scoreT = k2f(T);
    }
    __syncthreads();
    const float m = s_m;

    // ---- softmax denominator over selected set ----
    float part = 0.0f;
    for (int i = t; i < N_TOK; i += 1024) {
        if (f2k(scores[i]) > T) part += expf(scores[i] - m);
    }
    #pragma unroll
    for (int o = 16; o; o >>= 1) part += __shfl_xor_sync(0xFFFFFFFFu, part, o);
    if ((t & 31) == 0) fwred[t >> 5] = part;
    __syncthreads();
    if (t < 32) {
        float v = fwred[t];
        #pragma unroll
        for (int o = 16; o; o >>= 1) v += __shfl_xor_sync(0xFFFFFFFFu, v, o);
        if (t == 0) s_inv = 1.0f / (v + (float)need_eq * expf(s_scoreT - m));
    }
    __syncthreads();
    const float inv = s_inv;

    // ---- compact output ----
    unsigned* sel_i = g_sel_idx  + (size_t)e * CAP;
    float*    sel_p = g_sel_prob + (size_t)e * CAP;
    for (int i = t; i < N_TOK; i += 1024) {
        if (f2k(scores[i]) > T) {
            unsigned pos = atomicAdd(&s_na, 1u);
            sel_i[pos] = (unsigned)i;
            sel_p[pos] = expf(scores[i] - m) * inv;
            atomicAdd(&g_counts[i], 1);
        }
    }
    __syncthreads();
    unsigned ne = min(s_neq, 256u);
    if (t < (int)need_eq && t < (int)ne) {
        unsigned i = eqidx[t];
        unsigned pos = (CAP - need_eq) + t;
        sel_i[pos] = i;
        sel_p[pos] = expf(s_scoreT - m) * inv;
        atomicAdd(&g_counts[i], 1);
    }
}

// ---------------------------------------------------------------------------
// Kernel 3: emit — scatter compact lists into [N,E] outputs with count divide
// ---------------------------------------------------------------------------
__global__ void emit_kernel(float* __restrict__ out_w, float* __restrict__ out_a) {
    int idx = blockIdx.x * blockDim.x + threadIdx.x;
    if (idx >= E_EXP * CAP) return;
    int e = idx >> 8;                                  // CAP == 256
    unsigned i = g_sel_idx[idx];
    float p = g_sel_prob[idx];
    int c = g_counts[i];
    out_w[(size_t)i * E_EXP + e] = p / (float)c;
    out_a[(size_t)i * E_EXP + e] = 1.0f;
}

// ---------------------------------------------------------------------------
// launch
// ---------------------------------------------------------------------------
extern "C" void kernel_launch(void* const* d_in, const int* in_sizes, int n_in,
                              void* d_out, int out_size) {
    const float* tokens = (const float*)d_in[0];   // [4,4096,2048] fp32
    const float* wsel   = (const float*)d_in[1];   // [64,2048] fp32
    float* out = (float*)d_out;

    const int total_main = 2 * N_TOK * E_EXP;

    float* out_w;
    float* out_a;
    float* dummy_ptr = nullptr;
    cudaGetSymbolAddress((void**)&dummy_ptr, g_dummy);
    if (out_size >= total_main) {
        out_w = out;
        out_a = out + (size_t)N_TOK * E_EXP;
    } else if (out_size >= N_TOK * E_EXP) {
        out_w = out;
        out_a = dummy_ptr;
    } else {
        out_w = dummy_ptr;
        out_a = dummy_ptr;
    }

    cudaFuncSetAttribute(gemm_mma, cudaFuncAttributeMaxDynamicSharedMemorySize, GEMM_SMEM);
    cudaFuncSetAttribute(topk_kernel, cudaFuncAttributeMaxDynamicSharedMemorySize,
                         N_TOK * sizeof(float));

    // 0) init outputs + counts
    {
        int quads = (out_size + 3) / 4;
        int blocks = (quads + 255) / 256;
        init_kernel<<<blocks, 256>>>(out, out_size, total_main);
    }
    // 1) TF32x3 mma.sync GEMM -> g_aff
    gemm_mma<<<N_TOK / BMt, 256, GEMM_SMEM>>>(tokens, wsel);
    // 2) per-expert top-256 + softmax -> compact lists + counts
    topk_kernel<<<E_EXP, 1024, N_TOK * sizeof(float)>>>();
    // 3) emit outputs
    emit_kernel<<<(E_EXP * CAP + 127) / 128, 128>>>(out_w, out_a);
}